// round 4
// baseline (speedup 1.0000x reference)
#include <cuda_runtime.h>

// ---------------------------------------------------------------------------
// Compile-time filter construction (double precision, folded to fp32 imms)
// ---------------------------------------------------------------------------
__host__ __device__ constexpr double d_abs(double x){ return x < 0 ? -x : x; }
__host__ __device__ constexpr double cexp_pos(double x){ double t=1.0,s=1.0; for(int n=1;n<60;n++){ t*=x/n; s+=t; } return s; }
__host__ __device__ constexpr double cexp(double x){ return x < 0.0 ? 1.0/cexp_pos(-x) : cexp_pos(x); }
__host__ __device__ constexpr double ccos(double x){ double x2=x*x,t=1.0,s=1.0; for(int n=1;n<30;n++){ t*=-x2/((2.0*n-1.0)*(2.0*n)); s+=t; } return s; }

struct K7 { float w[7][7]; };

__host__ __device__ constexpr K7 make_log(int r, double sigma){
    double tmp[7][7] = {}; double s = 0.0;
    for(int i=-r;i<=r;i++) for(int j=-r;j<=r;j++){
        double r2 = (double)(i*i + j*j);
        double g  = cexp(-r2/(2.0*sigma*sigma));
        double f  = (1.0 - r2/(2.0*sigma*sigma))*g;
        tmp[i+3][j+3] = -f;
        s += d_abs(f);
    }
    K7 k{};
    for(int i=0;i<7;i++) for(int j=0;j<7;j++) k.w[i][j] = (float)(tmp[i][j]/s);
    return k;
}

__host__ __device__ constexpr K7 make_gabor(double c, double sn){
    double tmp[7][7] = {}; double s = 0.0;
    for(int i=0;i<7;i++) for(int j=0;j<7;j++){
        double x = (double)(j-3), y = (double)(i-3);
        double xt = x*c + y*sn;
        double g = cexp(-(x*x + y*y)/8.0) * ccos(2.0*3.14159265358979323846*0.1*xt);
        tmp[i][j] = g; s += d_abs(g);
    }
    K7 k{};
    for(int i=0;i<7;i++) for(int j=0;j<7;j++) k.w[i][j] = (float)(tmp[i][j]/s);
    return k;
}

__host__ __device__ constexpr K7 make_lpf(){
    K7 k{};
    double b[3] = {0.25, 0.5, 0.25};
    for(int i=0;i<3;i++) for(int j=0;j<3;j++) k.w[i+2][j+2] = (float)(b[i]*b[j]);
    return k;
}

__host__ __device__ constexpr K7 make_hpf3(){
    K7 k{};
    for(int i=2;i<=4;i++) for(int j=2;j<=4;j++) k.w[i][j] = -1.0f;
    k.w[3][3] = 8.0f;
    return k;
}
__host__ __device__ constexpr K7 make_hpf5(){
    K7 k{};
    for(int i=1;i<=5;i++) for(int j=1;j<=5;j++) k.w[i][j] = -1.0f;
    k.w[3][3] = 24.0f;
    return k;
}

// even / odd (in column) decomposition
__host__ __device__ constexpr K7 make_even(const K7& a){
    K7 k{};
    for(int i=0;i<7;i++) for(int j=0;j<7;j++) k.w[i][j] = (a.w[i][j] + a.w[i][6-j]) * 0.5f;
    return k;
}
__host__ __device__ constexpr K7 make_odd(const K7& a){
    K7 k{};
    for(int i=0;i<7;i++) for(int j=0;j<7;j++) k.w[i][j] = (a.w[i][j] - a.w[i][6-j]) * 0.5f;
    return k;
}

__device__ constexpr double RS2 = 0.70710678118654752440;
__device__ constexpr K7 KL3   = make_log(1, 0.8);
__device__ constexpr K7 KL5   = make_log(2, 1.0);
__device__ constexpr K7 KL7   = make_log(3, 1.4);
__device__ constexpr K7 KG0   = make_gabor( 1.0, 0.0);
__device__ constexpr K7 KG45  = make_gabor( RS2, RS2);
__device__ constexpr K7 KG90  = make_gabor( 0.0, 1.0);
__device__ constexpr K7 KGE   = make_even(KG45);   // shared even-even part of g45/g135
__device__ constexpr K7 KGO   = make_odd(KG45);    // odd-odd part (g45 = E+O, g135 = E-O)
__device__ constexpr K7 KLP   = make_lpf();
__device__ constexpr K7 KH3   = make_hpf3();
__device__ constexpr K7 KH5   = make_hpf5();

// ---------------------------------------------------------------------------
#define IMG_SZ 262144        // 512*512
#define PLANE  12582912      // 48*512*512

__device__ __forceinline__ float addi(float a, float b){
    float d; asm("fma.rn.f32 %0, %1, 0f3F800000, %2;" : "=f"(d) : "f"(a), "f"(b)); return d;
}
__device__ __forceinline__ float subi(float a, float b){   // a - b
    float d; asm("fma.rn.f32 %0, %1, 0fBF800000, %2;" : "=f"(d) : "f"(b), "f"(a)); return d;
}

__device__ __forceinline__ float tanh01(float z){    // tanh(0.1*z)
    float a = z * 0.28853900817779268f;              // 0.2 * log2(e)
    float t; asm("ex2.approx.f32 %0, %1;" : "=f"(t) : "f"(a));
    float den = t + 1.0f, rd;
    asm("rcp.approx.f32 %0, %1;" : "=f"(rd) : "f"(den));
    return (t - 1.0f) * rd;
}

struct Acc { float l3,l5,l7,h3,h5,lp,g0,g90,gE,gO,ctr; };

// Even-symmetric taps for fold-level R (R=0: center row, R=1..3: row pair 3±R).
template<int R>
__device__ __forceinline__ void taps_even(float vs0, float hs1, float hs2, float hs3, Acc& p){
    p.l7  = fmaf(vs0, KL7.w[3+R][3], p.l7);
    p.l7  = fmaf(hs1, KL7.w[3+R][4], p.l7);
    p.l7  = fmaf(hs2, KL7.w[3+R][5], p.l7);
    p.l7  = fmaf(hs3, KL7.w[3+R][6], p.l7);
    p.g0  = fmaf(vs0, KG0.w[3+R][3], p.g0);
    p.g0  = fmaf(hs1, KG0.w[3+R][4], p.g0);
    p.g0  = fmaf(hs2, KG0.w[3+R][5], p.g0);
    p.g0  = fmaf(hs3, KG0.w[3+R][6], p.g0);
    p.g90 = fmaf(vs0, KG90.w[3+R][3], p.g90);
    p.g90 = fmaf(hs1, KG90.w[3+R][4], p.g90);
    p.g90 = fmaf(hs2, KG90.w[3+R][5], p.g90);
    p.g90 = fmaf(hs3, KG90.w[3+R][6], p.g90);
    p.gE  = fmaf(vs0, KGE.w[3+R][3], p.gE);
    p.gE  = fmaf(hs1, KGE.w[3+R][4], p.gE);
    p.gE  = fmaf(hs2, KGE.w[3+R][5], p.gE);
    p.gE  = fmaf(hs3, KGE.w[3+R][6], p.gE);
    if constexpr (R <= 2){
        p.l5 = fmaf(vs0, KL5.w[3+R][3], p.l5);
        p.l5 = fmaf(hs1, KL5.w[3+R][4], p.l5);
        p.l5 = fmaf(hs2, KL5.w[3+R][5], p.l5);
        p.h5 = fmaf(vs0, KH5.w[3+R][3], p.h5);
        p.h5 = fmaf(hs1, KH5.w[3+R][4], p.h5);
        p.h5 = fmaf(hs2, KH5.w[3+R][5], p.h5);
    }
    if constexpr (R <= 1){
        p.l3 = fmaf(vs0, KL3.w[3+R][3], p.l3);
        p.l3 = fmaf(hs1, KL3.w[3+R][4], p.l3);
        p.lp = fmaf(vs0, KLP.w[3+R][3], p.lp);
        p.lp = fmaf(hs1, KLP.w[3+R][4], p.lp);
        p.h3 = fmaf(vs0, KH3.w[3+R][3], p.h3);
        p.h3 = fmaf(hs1, KH3.w[3+R][4], p.h3);
    }
    if constexpr (R == 0) p.ctr = vs0;
}

template<int R>
__device__ __forceinline__ void taps_odd(float hd1, float hd2, float hd3, Acc& p){
    p.gO = fmaf(hd1, KGO.w[3+R][4], p.gO);
    p.gO = fmaf(hd2, KGO.w[3+R][5], p.gO);
    p.gO = fmaf(hd3, KGO.w[3+R][6], p.gO);
}

// load 8 consecutive floats (8B-aligned) via 4x LDS.64
__device__ __forceinline__ void load8(const float* p, float v[8]){
    float2 a = *(const float2*)p;
    float2 b = *(const float2*)(p + 2);
    float2 c = *(const float2*)(p + 4);
    float2 d = *(const float2*)(p + 6);
    v[0]=a.x; v[1]=a.y; v[2]=b.x; v[3]=b.y;
    v[4]=c.x; v[5]=c.y; v[6]=d.x; v[7]=d.y;
}

__device__ __forceinline__ void finalize(const Acc& p, float& o, float& lf, float& lo, float& ho, float& go){
    o  = p.ctr;
    lf = p.lp;
    lo = fmaf(tanh01(fmaxf(fmaxf(p.l3, p.l5), p.l7)), 0.5f, 0.5f);
    ho = fmaf(tanh01(fmaxf(p.h3, p.h5)), 0.5f, 0.5f);
    // max(g45, g135) = gE + |gO|
    go = tanh01(fmaxf(fmaxf(p.g0, p.g90), p.gE + fabsf(p.gO)));
}

__global__ __launch_bounds__(512, 2)
void msfilters_kernel(const float* __restrict__ x, float* __restrict__ out, int planes){
    __shared__ __align__(16) float sm[22 * 72];

    const int img = blockIdx.z;
    const int x0 = blockIdx.x * 64;
    const int y0 = blockIdx.y * 16;
    const float* src = x + (size_t)img * IMG_SZ;

    // cooperative load of 22 x 70 halo tile (zero pad at image borders)
    for (int idx = threadIdx.x; idx < 22 * 70; idx += 512){
        int r = idx / 70;
        int c = idx - r * 70;
        int gy = y0 + r - 3;
        int gx = x0 + c - 3;
        float val = 0.0f;
        if ((unsigned)gy < 512u && (unsigned)gx < 512u) val = __ldg(src + gy * 512 + gx);
        sm[r * 72 + c] = val;
    }
    __syncthreads();

    const int tx2 = (threadIdx.x & 31) * 2;   // 32 threads x 2 px = 64 wide
    const int ty  =  threadIdx.x >> 5;        // 16 rows
    const float* base = &sm[(ty + 3) * 72 + tx2];

    Acc acc[2] = {};

    // ----- level 0: center row -----
    {
        float m[8]; load8(base, m);
        #pragma unroll
        for (int p = 0; p < 2; p++){
            const int cc = p + 3;
            float hs1 = addi(m[cc-1], m[cc+1]);
            float hs2 = addi(m[cc-2], m[cc+2]);
            float hs3 = addi(m[cc-3], m[cc+3]);
            taps_even<0>(m[cc], hs1, hs2, hs3, acc[p]);
        }
    }

    // ----- levels 1..3: folded row pairs -----
#define LEVEL(R) { \
        float T[8], B[8]; \
        load8(base - R * 72, T); \
        load8(base + R * 72, B); \
        float V[8], W[8]; \
        _Pragma("unroll") \
        for (int c = 0; c < 8; c++){ V[c] = addi(T[c], B[c]); W[c] = subi(T[c], B[c]); } \
        _Pragma("unroll") \
        for (int p = 0; p < 2; p++){ \
            const int cc = p + 3; \
            float hs1 = addi(V[cc-1], V[cc+1]); \
            float hs2 = addi(V[cc-2], V[cc+2]); \
            float hs3 = addi(V[cc-3], V[cc+3]); \
            taps_even<R>(V[cc], hs1, hs2, hs3, acc[p]); \
            float hd1 = subi(W[cc-1], W[cc+1]); \
            float hd2 = subi(W[cc-2], W[cc+2]); \
            float hd3 = subi(W[cc-3], W[cc+3]); \
            taps_odd<R>(hd1, hd2, hd3, acc[p]); \
        } }
    LEVEL(1)
    LEVEL(2)
    LEVEL(3)
#undef LEVEL

    float2 o2, lf2, lo2, ho2, go2;
    finalize(acc[0], o2.x, lf2.x, lo2.x, ho2.x, go2.x);
    finalize(acc[1], o2.y, lf2.y, lo2.y, ho2.y, go2.y);

    size_t obase = (size_t)img * IMG_SZ + (size_t)(y0 + ty) * 512 + x0 + tx2;
    *(float2*)(out + obase)                    = o2;
    *(float2*)(out + obase + (size_t)PLANE)    = lf2;
    *(float2*)(out + obase + 2*(size_t)PLANE)  = lo2;
    *(float2*)(out + obase + 3*(size_t)PLANE)  = ho2;
    if (planes >= 5)
        *(float2*)(out + obase + 4*(size_t)PLANE) = go2;
}

extern "C" void kernel_launch(void* const* d_in, const int* in_sizes, int n_in,
                              void* d_out, int out_size){
    const float* x = (const float*)d_in[0];
    float* out = (float*)d_out;
    const int planes = out_size / PLANE;   // 5 when use_gabor
    dim3 grid(8, 32, 48);
    dim3 block(512);
    msfilters_kernel<<<grid, block>>>(x, out, planes);
}

// round 5
// speedup vs baseline: 1.7114x; 1.7114x over previous
#include <cuda_runtime.h>

// ---------------------------------------------------------------------------
// Compile-time filter construction (double precision, folded to fp32 imms)
// ---------------------------------------------------------------------------
__host__ __device__ constexpr double d_abs(double x){ return x < 0 ? -x : x; }
__host__ __device__ constexpr double cexp_pos(double x){ double t=1.0,s=1.0; for(int n=1;n<60;n++){ t*=x/n; s+=t; } return s; }
__host__ __device__ constexpr double cexp(double x){ return x < 0.0 ? 1.0/cexp_pos(-x) : cexp_pos(x); }
__host__ __device__ constexpr double ccos(double x){ double x2=x*x,t=1.0,s=1.0; for(int n=1;n<30;n++){ t*=-x2/((2.0*n-1.0)*(2.0*n)); s+=t; } return s; }

struct K7 { float w[7][7]; };

__host__ __device__ constexpr K7 make_log(int r, double sigma){
    double tmp[7][7] = {}; double s = 0.0;
    for(int i=-r;i<=r;i++) for(int j=-r;j<=r;j++){
        double r2 = (double)(i*i + j*j);
        double g  = cexp(-r2/(2.0*sigma*sigma));
        double f  = (1.0 - r2/(2.0*sigma*sigma))*g;
        tmp[i+3][j+3] = -f;
        s += d_abs(f);
    }
    K7 k{};
    for(int i=0;i<7;i++) for(int j=0;j<7;j++) k.w[i][j] = (float)(tmp[i][j]/s);
    return k;
}

__host__ __device__ constexpr K7 make_gabor(double c, double sn){
    double tmp[7][7] = {}; double s = 0.0;
    for(int i=0;i<7;i++) for(int j=0;j<7;j++){
        double x = (double)(j-3), y = (double)(i-3);
        double xt = x*c + y*sn;
        double g = cexp(-(x*x + y*y)/8.0) * ccos(2.0*3.14159265358979323846*0.1*xt);
        tmp[i][j] = g; s += d_abs(g);
    }
    K7 k{};
    for(int i=0;i<7;i++) for(int j=0;j<7;j++) k.w[i][j] = (float)(tmp[i][j]/s);
    return k;
}

__host__ __device__ constexpr K7 make_lpf(){
    K7 k{};
    double b[3] = {0.25, 0.5, 0.25};
    for(int i=0;i<3;i++) for(int j=0;j<3;j++) k.w[i+2][j+2] = (float)(b[i]*b[j]);
    return k;
}

__host__ __device__ constexpr K7 make_hpf3(){
    K7 k{};
    for(int i=2;i<=4;i++) for(int j=2;j<=4;j++) k.w[i][j] = -1.0f;
    k.w[3][3] = 8.0f;
    return k;
}
__host__ __device__ constexpr K7 make_hpf5(){
    K7 k{};
    for(int i=1;i<=5;i++) for(int j=1;j<=5;j++) k.w[i][j] = -1.0f;
    k.w[3][3] = 24.0f;
    return k;
}

__host__ __device__ constexpr K7 make_even(const K7& a){
    K7 k{};
    for(int i=0;i<7;i++) for(int j=0;j<7;j++) k.w[i][j] = (a.w[i][j] + a.w[i][6-j]) * 0.5f;
    return k;
}
__host__ __device__ constexpr K7 make_odd(const K7& a){
    K7 k{};
    for(int i=0;i<7;i++) for(int j=0;j<7;j++) k.w[i][j] = (a.w[i][j] - a.w[i][6-j]) * 0.5f;
    return k;
}

__device__ constexpr double RS2 = 0.70710678118654752440;
__device__ constexpr K7 KL3   = make_log(1, 0.8);
__device__ constexpr K7 KL5   = make_log(2, 1.0);
__device__ constexpr K7 KL7   = make_log(3, 1.4);
__device__ constexpr K7 KG0   = make_gabor( 1.0, 0.0);
__device__ constexpr K7 KG45  = make_gabor( RS2, RS2);
__device__ constexpr K7 KG90  = make_gabor( 0.0, 1.0);
__device__ constexpr K7 KGE   = make_even(KG45);
__device__ constexpr K7 KGO   = make_odd(KG45);
__device__ constexpr K7 KLP   = make_lpf();
__device__ constexpr K7 KH3   = make_hpf3();
__device__ constexpr K7 KH5   = make_hpf5();

// ---------------------------------------------------------------------------
#define IMG_SZ 262144        // 512*512
#define PLANE  12582912      // 48*512*512

__device__ __forceinline__ float addi(float a, float b){
    float d; asm("fma.rn.f32 %0, %1, 0f3F800000, %2;" : "=f"(d) : "f"(a), "f"(b)); return d;
}
__device__ __forceinline__ float subi(float a, float b){   // a - b
    float d; asm("fma.rn.f32 %0, %1, 0fBF800000, %2;" : "=f"(d) : "f"(b), "f"(a)); return d;
}

__device__ __forceinline__ float tanh01(float z){    // tanh(0.1*z)
    float a = z * 0.28853900817779268f;              // 0.2 * log2(e)
    float t; asm("ex2.approx.f32 %0, %1;" : "=f"(t) : "f"(a));
    float den = t + 1.0f, rd;
    asm("rcp.approx.f32 %0, %1;" : "=f"(rd) : "f"(den));
    return (t - 1.0f) * rd;
}

struct Acc { float l3,l5,l7,h3,h5,lp,g0,g90,gE,gO,ctr; };

template<int R>
__device__ __forceinline__ void taps_even(float vs0, float hs1, float hs2, float hs3, Acc& p){
    p.l7  = fmaf(vs0, KL7.w[3+R][3], p.l7);
    p.l7  = fmaf(hs1, KL7.w[3+R][4], p.l7);
    p.l7  = fmaf(hs2, KL7.w[3+R][5], p.l7);
    p.l7  = fmaf(hs3, KL7.w[3+R][6], p.l7);
    p.g0  = fmaf(vs0, KG0.w[3+R][3], p.g0);
    p.g0  = fmaf(hs1, KG0.w[3+R][4], p.g0);
    p.g0  = fmaf(hs2, KG0.w[3+R][5], p.g0);
    p.g0  = fmaf(hs3, KG0.w[3+R][6], p.g0);
    p.g90 = fmaf(vs0, KG90.w[3+R][3], p.g90);
    p.g90 = fmaf(hs1, KG90.w[3+R][4], p.g90);
    p.g90 = fmaf(hs2, KG90.w[3+R][5], p.g90);
    p.g90 = fmaf(hs3, KG90.w[3+R][6], p.g90);
    p.gE  = fmaf(vs0, KGE.w[3+R][3], p.gE);
    p.gE  = fmaf(hs1, KGE.w[3+R][4], p.gE);
    p.gE  = fmaf(hs2, KGE.w[3+R][5], p.gE);
    p.gE  = fmaf(hs3, KGE.w[3+R][6], p.gE);
    if constexpr (R <= 2){
        p.l5 = fmaf(vs0, KL5.w[3+R][3], p.l5);
        p.l5 = fmaf(hs1, KL5.w[3+R][4], p.l5);
        p.l5 = fmaf(hs2, KL5.w[3+R][5], p.l5);
        p.h5 = fmaf(vs0, KH5.w[3+R][3], p.h5);
        p.h5 = fmaf(hs1, KH5.w[3+R][4], p.h5);
        p.h5 = fmaf(hs2, KH5.w[3+R][5], p.h5);
    }
    if constexpr (R <= 1){
        p.l3 = fmaf(vs0, KL3.w[3+R][3], p.l3);
        p.l3 = fmaf(hs1, KL3.w[3+R][4], p.l3);
        p.lp = fmaf(vs0, KLP.w[3+R][3], p.lp);
        p.lp = fmaf(hs1, KLP.w[3+R][4], p.lp);
        p.h3 = fmaf(vs0, KH3.w[3+R][3], p.h3);
        p.h3 = fmaf(hs1, KH3.w[3+R][4], p.h3);
    }
    if constexpr (R == 0) p.ctr = vs0;
}

template<int R>
__device__ __forceinline__ void taps_odd(float hd1, float hd2, float hd3, Acc& p){
    p.gO = fmaf(hd1, KGO.w[3+R][4], p.gO);
    p.gO = fmaf(hd2, KGO.w[3+R][5], p.gO);
    p.gO = fmaf(hd3, KGO.w[3+R][6], p.gO);
}

__device__ __forceinline__ void load10(const float* p, float v[10]){
    float4 a = *(const float4*)p;
    float4 b = *(const float4*)(p + 4);
    float2 c = *(const float2*)(p + 8);
    v[0]=a.x; v[1]=a.y; v[2]=a.z; v[3]=a.w;
    v[4]=b.x; v[5]=b.y; v[6]=b.z; v[7]=b.w;
    v[8]=c.x; v[9]=c.y;
}

__device__ __forceinline__ void finalize(const Acc& p, float& o, float& lf, float& lo, float& ho, float& go){
    o  = p.ctr;
    lf = p.lp;
    lo = fmaf(tanh01(fmaxf(fmaxf(p.l3, p.l5), p.l7)), 0.5f, 0.5f);
    ho = fmaf(tanh01(fmaxf(p.h3, p.h5)), 0.5f, 0.5f);
    go = tanh01(fmaxf(fmaxf(p.g0, p.g90), p.gE + fabsf(p.gO)));
}

// Persistent-strip kernel: each block does a 64-wide x 128-tall strip in
// 8 iterations of 16 rows, with a circular 32-row smem window and
// register-prefetched row loads overlapping compute.
#define STRIP_H 128
#define ITERS   8            // STRIP_H / 16

__global__ __launch_bounds__(256, 3)
void msfilters_kernel(const float* __restrict__ x, float* __restrict__ out, int planes){
    __shared__ __align__(16) float sm[32 * 72];

    const int img    = blockIdx.z;
    const int x0     = blockIdx.x * 64;
    const int ystart = blockIdx.y * STRIP_H;
    const float* src = x + (size_t)img * IMG_SZ;

    // initial fill: logical rows -3..18  (phys row = (logical+3)&31)
    for (int idx = threadIdx.x; idx < 22 * 70; idx += 256){
        int r = idx / 70;                 // 0..21 -> logical y = r-3
        int c = idx - r * 70;
        int gy = ystart + r - 3;
        int gx = x0 + c - 3;
        float val = 0.0f;
        if ((unsigned)gy < 512u && (unsigned)gx < 512u) val = __ldg(src + gy * 512 + gx);
        sm[(r & 31) * 72 + c] = val;
    }
    __syncthreads();

    const int tx4 = (threadIdx.x & 15) * 4;   // 16 threads x 4 px = 64 wide
    const int ty  =  threadIdx.x >> 4;        // 16 rows

    for (int k = 0; k < ITERS; k++){
        // ---- prefetch next 16 rows (logical 16k+19 .. 16k+34) into regs ----
        float pf[5];
        const bool havepf = (k < ITERS - 1);
        if (havepf){
            #pragma unroll
            for (int j = 0; j < 5; j++){
                int idx = threadIdx.x + j * 256;
                float val = 0.0f;
                if (idx < 16 * 70){
                    int r = idx / 70;
                    int c = idx - r * 70;
                    int gy = ystart + 16 * k + 19 + r;
                    int gx = x0 + c - 3;
                    if ((unsigned)gy < 512u && (unsigned)gx < 512u)
                        val = __ldg(src + gy * 512 + gx);
                }
                pf[j] = val;
            }
        }

        // ---- compute rows 16k+ty from circular smem window ----
        const int yb = 16 * k + ty + 3;   // logical+3 of center row
        const float* rowp[7];
        #pragma unroll
        for (int d = 0; d < 7; d++)
            rowp[d] = &sm[((yb + d - 3) & 31) * 72 + tx4];

        Acc acc[4] = {};

        {   // level 0: center row
            float m[10]; load10(rowp[3], m);
            #pragma unroll
            for (int p = 0; p < 4; p++){
                const int cc = p + 3;
                float hs1 = addi(m[cc-1], m[cc+1]);
                float hs2 = addi(m[cc-2], m[cc+2]);
                float hs3 = addi(m[cc-3], m[cc+3]);
                taps_even<0>(m[cc], hs1, hs2, hs3, acc[p]);
            }
        }

#define LEVEL(R) { \
        float T[10], B[10]; \
        load10(rowp[3-R], T); \
        load10(rowp[3+R], B); \
        float V[10], W[10]; \
        _Pragma("unroll") \
        for (int c = 0; c < 10; c++){ V[c] = addi(T[c], B[c]); W[c] = subi(T[c], B[c]); } \
        _Pragma("unroll") \
        for (int p = 0; p < 4; p++){ \
            const int cc = p + 3; \
            float hs1 = addi(V[cc-1], V[cc+1]); \
            float hs2 = addi(V[cc-2], V[cc+2]); \
            float hs3 = addi(V[cc-3], V[cc+3]); \
            taps_even<R>(V[cc], hs1, hs2, hs3, acc[p]); \
            float hd1 = subi(W[cc-1], W[cc+1]); \
            float hd2 = subi(W[cc-2], W[cc+2]); \
            float hd3 = subi(W[cc-3], W[cc+3]); \
            taps_odd<R>(hd1, hd2, hd3, acc[p]); \
        } }
        LEVEL(1)
        LEVEL(2)
        LEVEL(3)
#undef LEVEL

        float4 o4, lf4, lo4, ho4, go4;
        finalize(acc[0], o4.x, lf4.x, lo4.x, ho4.x, go4.x);
        finalize(acc[1], o4.y, lf4.y, lo4.y, ho4.y, go4.y);
        finalize(acc[2], o4.z, lf4.z, lo4.z, ho4.z, go4.z);
        finalize(acc[3], o4.w, lf4.w, lo4.w, ho4.w, go4.w);

        size_t obase = (size_t)img * IMG_SZ + (size_t)(ystart + 16 * k + ty) * 512 + x0 + tx4;
        *(float4*)(out + obase)                    = o4;
        *(float4*)(out + obase + (size_t)PLANE)    = lf4;
        *(float4*)(out + obase + 2*(size_t)PLANE)  = lo4;
        *(float4*)(out + obase + 3*(size_t)PLANE)  = ho4;
        if (planes >= 5)
            *(float4*)(out + obase + 4*(size_t)PLANE) = go4;

        // ---- commit prefetched rows to circular buffer ----
        __syncthreads();
        if (havepf){
            #pragma unroll
            for (int j = 0; j < 5; j++){
                int idx = threadIdx.x + j * 256;
                if (idx < 16 * 70){
                    int r = idx / 70;
                    int c = idx - r * 70;
                    int ylog = 16 * k + 19 + r;
                    sm[((ylog + 3) & 31) * 72 + c] = pf[j];
                }
            }
        }
        __syncthreads();
    }
}

extern "C" void kernel_launch(void* const* d_in, const int* in_sizes, int n_in,
                              void* d_out, int out_size){
    const float* x = (const float*)d_in[0];
    float* out = (float*)d_out;
    const int planes = out_size / PLANE;   // 5 when use_gabor
    dim3 grid(8, 512 / STRIP_H, 48);
    dim3 block(256);
    msfilters_kernel<<<grid, block>>>(x, out, planes);
}